// round 1
// baseline (speedup 1.0000x reference)
#include <cuda_runtime.h>
#include <cuda_bf16.h>
#include <cstdint>

// ---------------------------------------------------------------------------
// NeuralODE: x_{t+1} = x_t + dt_scale*DT * (tanh(tanh(x W1 + b1) W2 + b2) W3 + b3)
// B=4096 rows are independent -> persistent kernel, weights cached in smem,
// all 200 steps inside one launch. bf16 mma.sync with f32 accumulation.
// ---------------------------------------------------------------------------

namespace {

constexpr int B_    = 4096;
constexpr int S_    = 64;
constexpr int H_    = 256;
constexpr int MROWS = 32;              // rows per CTA
constexpr int CTAS  = B_ / MROWS;      // 128
constexpr int NTH   = 256;             // 8 warps

// u32 strides for activation buffers (pad so stride % 8 == 4 -> conflict-free
// A-fragment loads: bank = 4*g + t)
constexpr int HSTR = 132;              // 128 pairs + 4 pad
constexpr int XSTR = 36;               // 32 pairs + 4 pad

// smem layout (bytes)
constexpr int SM_W1P0 = 0;                           // 16384
constexpr int SM_W1P1 = SM_W1P0 + 16384;             // 16384
constexpr int SM_W2P0 = SM_W1P1 + 16384;             // 65536
constexpr int SM_W2P1 = SM_W2P0 + 65536;             // 65536
constexpr int SM_W3P0 = SM_W2P1 + 65536;             // 16384
constexpr int SM_W3P1 = SM_W3P0 + 16384;             // 16384
constexpr int SM_H    = SM_W3P1 + 16384;             // 32*132*4 = 16896
constexpr int SM_XB   = SM_H + MROWS * HSTR * 4;     // 32*36*4  = 4608
constexpr int SM_B1   = SM_XB + MROWS * XSTR * 4;    // 1024
constexpr int SM_B2   = SM_B1 + 1024;                // 1024
constexpr int SM_B3   = SM_B2 + 1024;                // 256
constexpr int SMEM_BYTES = SM_B3 + 256;              // 220416 total

__device__ __forceinline__ uint32_t pack_bf16(float lo, float hi) {
    __nv_bfloat162 v = __floats2bfloat162_rn(lo, hi);
    return *reinterpret_cast<uint32_t*>(&v);
}

__device__ __forceinline__ float tanh_ap(float x) {
    float y;
    asm("tanh.approx.f32 %0, %1;" : "=f"(y) : "f"(x));
    return y;
}

__device__ __forceinline__ void mma16816(float* d,
                                         uint32_t a0, uint32_t a1, uint32_t a2, uint32_t a3,
                                         uint32_t b0, uint32_t b1) {
    asm volatile(
        "mma.sync.aligned.m16n8k16.row.col.f32.bf16.bf16.f32 "
        "{%0,%1,%2,%3},{%4,%5,%6,%7},{%8,%9},{%0,%1,%2,%3};\n"
        : "+f"(d[0]), "+f"(d[1]), "+f"(d[2]), "+f"(d[3])
        : "r"(a0), "r"(a1), "r"(a2), "r"(a3), "r"(b0), "r"(b1));
}

// Shuffle a fp32 weight matrix W[K][N] (row-major, N = row stride) into one
// bf16x2 B-fragment plane. Plane layout (u32 index):
//   idx = ((nt*NKB + kb)*4 + t)*8 + g   with n = nt*8+g, k0 = kb*16 + t*2 + koff
//   value = pack(W[k0][n], W[k0+1][n])
// g fast axis -> LDS bank = g + 8*t, 32 distinct banks: conflict-free loads.
template <int NKB, int LOG2NKB>
__device__ void fill_plane(uint32_t* plane, const float* __restrict__ W,
                           int N, int koff, int tid) {
    const int total = (N / 8) * NKB * 4 * 8;   // = N * NKB * 4
    for (int e = tid; e < total; e += NTH) {
        int gg   = e & 7;
        int tt   = (e >> 3) & 3;
        int kbnt = e >> 5;
        int kb   = kbnt & (NKB - 1);
        int nt   = kbnt >> LOG2NKB;
        int n    = nt * 8 + gg;
        int k0   = kb * 16 + tt * 2 + koff;
        plane[e] = pack_bf16(W[k0 * N + n], W[(k0 + 1) * N + n]);
    }
}

} // namespace

extern "C" __global__ void __launch_bounds__(NTH, 1)
neuralode_persistent_kernel(const float* __restrict__ x0,
                            const float* __restrict__ W1, const float* __restrict__ b1,
                            const float* __restrict__ W2, const float* __restrict__ b2,
                            const float* __restrict__ W3, const float* __restrict__ b3,
                            const float* __restrict__ dt_scale,
                            const int*   __restrict__ num_steps,
                            float* __restrict__ out)
{
    extern __shared__ unsigned char smem_raw[];
    uint32_t* w1p0 = reinterpret_cast<uint32_t*>(smem_raw + SM_W1P0);
    uint32_t* w1p1 = reinterpret_cast<uint32_t*>(smem_raw + SM_W1P1);
    uint32_t* w2p0 = reinterpret_cast<uint32_t*>(smem_raw + SM_W2P0);
    uint32_t* w2p1 = reinterpret_cast<uint32_t*>(smem_raw + SM_W2P1);
    uint32_t* w3p0 = reinterpret_cast<uint32_t*>(smem_raw + SM_W3P0);
    uint32_t* w3p1 = reinterpret_cast<uint32_t*>(smem_raw + SM_W3P1);
    uint32_t* hbuf = reinterpret_cast<uint32_t*>(smem_raw + SM_H);
    uint32_t* xb   = reinterpret_cast<uint32_t*>(smem_raw + SM_XB);
    float*    sb1  = reinterpret_cast<float*>(smem_raw + SM_B1);
    float*    sb2  = reinterpret_cast<float*>(smem_raw + SM_B2);
    float*    sb3  = reinterpret_cast<float*>(smem_raw + SM_B3);

    const int tid = threadIdx.x;

    // ---- one-time weight shuffle into fragment-ordered smem planes ----
    fill_plane<4, 2>(w1p0, W1, H_, 0, tid);
    fill_plane<4, 2>(w1p1, W1, H_, 8, tid);
    fill_plane<16, 4>(w2p0, W2, H_, 0, tid);
    fill_plane<16, 4>(w2p1, W2, H_, 8, tid);
    fill_plane<16, 4>(w3p0, W3, S_, 0, tid);
    fill_plane<16, 4>(w3p1, W3, S_, 8, tid);
    if (tid < H_) { sb1[tid] = b1[tid]; sb2[tid] = b2[tid]; }
    if (tid < S_) { sb3[tid] = b3[tid]; }

    const int   nsteps  = num_steps[0];
    const float dts     = dt_scale[0] * 0.01f;
    const int   row0    = blockIdx.x * MROWS;
    const long  ostride = (long)(nsteps + 1) * S_;

    // ---- t=0: trajectory[., 0, .] = x0 ----
    for (int i = tid; i < MROWS * S_; i += NTH) {
        int r = i >> 6, c = i & 63;
        out[(long)(row0 + r) * ostride + c] = x0[(row0 + r) * S_ + c];
    }

    // ---- warp/lane decomposition ----
    const int warp = tid >> 5, lane = tid & 31;
    const int g = lane >> 2, t = lane & 3;
    const int mt    = warp & 1;        // m-tile (16 rows)
    const int ng    = warp >> 1;       // 0..3
    const int nt1_0 = ng * 8;          // GEMM1/2: 8 n-tiles per warp
    const int nt3_0 = ng * 2;          // GEMM3:   2 n-tiles per warp
    const int r0l   = mt * 16 + g;     // local row for c0/c1 (a0/a2)
    const int tg    = t * 8 + g;       // fast index into B planes

    // ---- x state lives in registers in GEMM3-fragment layout ----
    float xr[2][4];
#pragma unroll
    for (int j = 0; j < 2; ++j) {
        int colb = (nt3_0 + j) * 8 + t * 2;
        const float* p = x0 + (long)(row0 + r0l) * S_ + colb;
        xr[j][0] = p[0];
        xr[j][1] = p[1];
        xr[j][2] = p[8 * S_];
        xr[j][3] = p[8 * S_ + 1];
    }
#pragma unroll
    for (int j = 0; j < 2; ++j) {
        int pidx = (nt3_0 + j) * 4 + t;
        xb[r0l * XSTR + pidx]       = pack_bf16(xr[j][0], xr[j][1]);
        xb[(r0l + 8) * XSTR + pidx] = pack_bf16(xr[j][2], xr[j][3]);
    }
    __syncthreads();

    // ======================= main time-step loop ==========================
    for (int step = 0; step < nsteps; ++step) {
        float acc[8][4];

        // ---- GEMM1: [32,64] @ W1[64,256] ----
#pragma unroll
        for (int j = 0; j < 8; ++j)
#pragma unroll
            for (int q = 0; q < 4; ++q) acc[j][q] = 0.f;

#pragma unroll
        for (int kb = 0; kb < 4; ++kb) {
            const uint32_t* ap = xb + r0l * XSTR + kb * 8 + t;
            uint32_t a0 = ap[0], a2 = ap[4];
            uint32_t a1 = ap[8 * XSTR], a3 = ap[8 * XSTR + 4];
#pragma unroll
            for (int j = 0; j < 8; ++j) {
                int idx = ((nt1_0 + j) * 4 + kb) * 32 + tg;
                mma16816(acc[j], a0, a1, a2, a3, w1p0[idx], w1p1[idx]);
            }
        }
        // epilogue1: h = tanh(acc + b1)  (hbuf free: prev step fully consumed)
#pragma unroll
        for (int j = 0; j < 8; ++j) {
            int colb = (nt1_0 + j) * 8 + t * 2;
            float bb0 = sb1[colb], bb1 = sb1[colb + 1];
            int pidx = (nt1_0 + j) * 4 + t;
            hbuf[r0l * HSTR + pidx] =
                pack_bf16(tanh_ap(acc[j][0] + bb0), tanh_ap(acc[j][1] + bb1));
            hbuf[(r0l + 8) * HSTR + pidx] =
                pack_bf16(tanh_ap(acc[j][2] + bb0), tanh_ap(acc[j][3] + bb1));
        }
        __syncthreads();

        // ---- GEMM2: [32,256] @ W2[256,256] ----
#pragma unroll
        for (int j = 0; j < 8; ++j)
#pragma unroll
            for (int q = 0; q < 4; ++q) acc[j][q] = 0.f;

#pragma unroll 4
        for (int kb = 0; kb < 16; ++kb) {
            const uint32_t* ap = hbuf + r0l * HSTR + kb * 8 + t;
            uint32_t a0 = ap[0], a2 = ap[4];
            uint32_t a1 = ap[8 * HSTR], a3 = ap[8 * HSTR + 4];
#pragma unroll
            for (int j = 0; j < 8; ++j) {
                int idx = ((nt1_0 + j) * 16 + kb) * 32 + tg;
                mma16816(acc[j], a0, a1, a2, a3, w2p0[idx], w2p1[idx]);
            }
        }
        __syncthreads();   // all reads of hbuf done before overwrite

        // epilogue2: h = tanh(acc + b2) (in place)
#pragma unroll
        for (int j = 0; j < 8; ++j) {
            int colb = (nt1_0 + j) * 8 + t * 2;
            float bb0 = sb2[colb], bb1 = sb2[colb + 1];
            int pidx = (nt1_0 + j) * 4 + t;
            hbuf[r0l * HSTR + pidx] =
                pack_bf16(tanh_ap(acc[j][0] + bb0), tanh_ap(acc[j][1] + bb1));
            hbuf[(r0l + 8) * HSTR + pidx] =
                pack_bf16(tanh_ap(acc[j][2] + bb0), tanh_ap(acc[j][3] + bb1));
        }
        __syncthreads();

        // ---- GEMM3: [32,256] @ W3[256,64] ----
        float acc3[2][4];
#pragma unroll
        for (int j = 0; j < 2; ++j)
#pragma unroll
            for (int q = 0; q < 4; ++q) acc3[j][q] = 0.f;

#pragma unroll 4
        for (int kb = 0; kb < 16; ++kb) {
            const uint32_t* ap = hbuf + r0l * HSTR + kb * 8 + t;
            uint32_t a0 = ap[0], a2 = ap[4];
            uint32_t a1 = ap[8 * HSTR], a3 = ap[8 * HSTR + 4];
#pragma unroll
            for (int j = 0; j < 2; ++j) {
                int idx = ((nt3_0 + j) * 16 + kb) * 32 + tg;
                mma16816(acc3[j], a0, a1, a2, a3, w3p0[idx], w3p1[idx]);
            }
        }

        // epilogue3: x += (acc3 + b3) * dts ; write trajectory + refresh xb
        float* orow = out + (long)(row0 + r0l) * ostride + (long)(step + 1) * S_;
#pragma unroll
        for (int j = 0; j < 2; ++j) {
            int colb = (nt3_0 + j) * 8 + t * 2;
            float bb0 = sb3[colb], bb1 = sb3[colb + 1];
            xr[j][0] += (acc3[j][0] + bb0) * dts;
            xr[j][1] += (acc3[j][1] + bb1) * dts;
            xr[j][2] += (acc3[j][2] + bb0) * dts;
            xr[j][3] += (acc3[j][3] + bb1) * dts;
            *reinterpret_cast<float2*>(orow + colb) =
                make_float2(xr[j][0], xr[j][1]);
            *reinterpret_cast<float2*>(orow + colb + 8 * ostride) =
                make_float2(xr[j][2], xr[j][3]);
            int pidx = (nt3_0 + j) * 4 + t;
            xb[r0l * XSTR + pidx]       = pack_bf16(xr[j][0], xr[j][1]);
            xb[(r0l + 8) * XSTR + pidx] = pack_bf16(xr[j][2], xr[j][3]);
        }
        __syncthreads();
    }
}

extern "C" void kernel_launch(void* const* d_in, const int* in_sizes, int n_in,
                              void* d_out, int out_size)
{
    (void)in_sizes; (void)n_in; (void)out_size;
    const float* x0       = (const float*)d_in[0];
    const float* W1       = (const float*)d_in[1];
    const float* b1       = (const float*)d_in[2];
    const float* W2       = (const float*)d_in[3];
    const float* b2       = (const float*)d_in[4];
    const float* W3       = (const float*)d_in[5];
    const float* b3       = (const float*)d_in[6];
    const float* dt_scale = (const float*)d_in[7];
    const int*   nsteps   = (const int*)d_in[8];
    float*       out      = (float*)d_out;

    cudaFuncSetAttribute(neuralode_persistent_kernel,
                         cudaFuncAttributeMaxDynamicSharedMemorySize, SMEM_BYTES);
    neuralode_persistent_kernel<<<CTAS, NTH, SMEM_BYTES>>>(
        x0, W1, b1, W2, b2, W3, b3, dt_scale, nsteps, out);
}

// round 2
// speedup vs baseline: 1.0409x; 1.0409x over previous
#include <cuda_runtime.h>
#include <cuda_bf16.h>
#include <cstdint>

// ---------------------------------------------------------------------------
// NeuralODE persistent kernel, round 2:
//  - 512 threads (16 warps): 2 m-tiles x 8 n-column groups
//  - per-m-tile named barriers (the two 16-row halves are fully independent)
//  - streaming trajectory stores
// ---------------------------------------------------------------------------

namespace {

constexpr int B_    = 4096;
constexpr int S_    = 64;
constexpr int H_    = 256;
constexpr int MROWS = 32;              // rows per CTA
constexpr int CTAS  = B_ / MROWS;      // 128
constexpr int NTH   = 512;             // 16 warps

// u32 strides for activation buffers (stride % 8 == 4 -> conflict-free
// A-fragment loads: bank = (4*g + t) % 32)
constexpr int HSTR = 132;              // 128 pairs + 4 pad
constexpr int XSTR = 36;               // 32 pairs + 4 pad

// smem layout (bytes)
constexpr int SM_W1P0 = 0;                           // 16384
constexpr int SM_W1P1 = SM_W1P0 + 16384;
constexpr int SM_W2P0 = SM_W1P1 + 16384;             // 65536
constexpr int SM_W2P1 = SM_W2P0 + 65536;
constexpr int SM_W3P0 = SM_W2P1 + 65536;             // 16384
constexpr int SM_W3P1 = SM_W3P0 + 16384;
constexpr int SM_H    = SM_W3P1 + 16384;             // 16896
constexpr int SM_XB   = SM_H + MROWS * HSTR * 4;     // 4608
constexpr int SM_B1   = SM_XB + MROWS * XSTR * 4;    // 1024
constexpr int SM_B2   = SM_B1 + 1024;                // 1024
constexpr int SM_B3   = SM_B2 + 1024;                // 256
constexpr int SMEM_BYTES = SM_B3 + 256;              // 220416

__device__ __forceinline__ uint32_t pack_bf16(float lo, float hi) {
    __nv_bfloat162 v = __floats2bfloat162_rn(lo, hi);
    return *reinterpret_cast<uint32_t*>(&v);
}

__device__ __forceinline__ float tanh_ap(float x) {
    float y;
    asm("tanh.approx.f32 %0, %1;" : "=f"(y) : "f"(x));
    return y;
}

__device__ __forceinline__ void mma16816(float* d,
                                         uint32_t a0, uint32_t a1, uint32_t a2, uint32_t a3,
                                         uint32_t b0, uint32_t b1) {
    asm volatile(
        "mma.sync.aligned.m16n8k16.row.col.f32.bf16.bf16.f32 "
        "{%0,%1,%2,%3},{%4,%5,%6,%7},{%8,%9},{%0,%1,%2,%3};\n"
        : "+f"(d[0]), "+f"(d[1]), "+f"(d[2]), "+f"(d[3])
        : "r"(a0), "r"(a1), "r"(a2), "r"(a3), "r"(b0), "r"(b1));
}

// m-tile scoped barrier: 8 warps (256 threads) of one 16-row half.
__device__ __forceinline__ void bar_mt(int mt) {
    asm volatile("bar.sync %0, 256;" :: "r"(mt + 1) : "memory");
}

// Shuffle fp32 W[K][N] (row-major) into one bf16x2 B-fragment plane.
//   idx = ((nt*NKB + kb)*4 + t)*8 + g ; n = nt*8+g ; k0 = kb*16 + t*2 + koff
// g fast axis -> conflict-free LDS.32 (bank = g + 8t).
template <int NKB, int LOG2NKB>
__device__ void fill_plane(uint32_t* plane, const float* __restrict__ W,
                           int N, int koff, int tid) {
    const int total = N * NKB * 4;
    for (int e = tid; e < total; e += NTH) {
        int gg   = e & 7;
        int tt   = (e >> 3) & 3;
        int kbnt = e >> 5;
        int kb   = kbnt & (NKB - 1);
        int nt   = kbnt >> LOG2NKB;
        int n    = nt * 8 + gg;
        int k0   = kb * 16 + tt * 2 + koff;
        plane[e] = pack_bf16(W[k0 * N + n], W[(k0 + 1) * N + n]);
    }
}

} // namespace

extern "C" __global__ void __launch_bounds__(NTH, 1)
neuralode_persistent_kernel(const float* __restrict__ x0,
                            const float* __restrict__ W1, const float* __restrict__ b1,
                            const float* __restrict__ W2, const float* __restrict__ b2,
                            const float* __restrict__ W3, const float* __restrict__ b3,
                            const float* __restrict__ dt_scale,
                            const int*   __restrict__ num_steps,
                            float* __restrict__ out)
{
    extern __shared__ unsigned char smem_raw[];
    uint32_t* w1p0 = reinterpret_cast<uint32_t*>(smem_raw + SM_W1P0);
    uint32_t* w1p1 = reinterpret_cast<uint32_t*>(smem_raw + SM_W1P1);
    uint32_t* w2p0 = reinterpret_cast<uint32_t*>(smem_raw + SM_W2P0);
    uint32_t* w2p1 = reinterpret_cast<uint32_t*>(smem_raw + SM_W2P1);
    uint32_t* w3p0 = reinterpret_cast<uint32_t*>(smem_raw + SM_W3P0);
    uint32_t* w3p1 = reinterpret_cast<uint32_t*>(smem_raw + SM_W3P1);
    uint32_t* hbuf = reinterpret_cast<uint32_t*>(smem_raw + SM_H);
    uint32_t* xb   = reinterpret_cast<uint32_t*>(smem_raw + SM_XB);
    float*    sb1  = reinterpret_cast<float*>(smem_raw + SM_B1);
    float*    sb2  = reinterpret_cast<float*>(smem_raw + SM_B2);
    float*    sb3  = reinterpret_cast<float*>(smem_raw + SM_B3);

    const int tid = threadIdx.x;

    // ---- one-time weight shuffle into fragment-ordered smem planes ----
    fill_plane<4, 2>(w1p0, W1, H_, 0, tid);
    fill_plane<4, 2>(w1p1, W1, H_, 8, tid);
    fill_plane<16, 4>(w2p0, W2, H_, 0, tid);
    fill_plane<16, 4>(w2p1, W2, H_, 8, tid);
    fill_plane<16, 4>(w3p0, W3, S_, 0, tid);
    fill_plane<16, 4>(w3p1, W3, S_, 8, tid);
    if (tid < H_) { sb1[tid] = b1[tid]; sb2[tid] = b2[tid]; }
    if (tid < S_) { sb3[tid] = b3[tid]; }

    const int   nsteps  = num_steps[0];
    const float dts     = dt_scale[0] * 0.01f;
    const int   row0    = blockIdx.x * MROWS;
    const long  ostride = (long)(nsteps + 1) * S_;

    // ---- t=0: trajectory[., 0, .] = x0 ----
    for (int i = tid; i < MROWS * S_; i += NTH) {
        int r = i >> 6, c = i & 63;
        out[(long)(row0 + r) * ostride + c] = x0[(row0 + r) * S_ + c];
    }

    // ---- warp/lane decomposition: 16 warps = 2 m-tiles x 8 n-groups ----
    const int warp = tid >> 5, lane = tid & 31;
    const int g = lane >> 2, t = lane & 3;
    const int mt    = warp & 1;        // m-tile (16 rows)
    const int ng    = warp >> 1;       // 0..7 column group
    const int nt1_0 = ng * 4;          // GEMM1/2: 4 n-tiles per warp
    const int nt3   = ng;              // GEMM3:   1 n-tile per warp
    const int r0l   = mt * 16 + g;     // local row for c0/c1 (a0/a2)
    const int tg    = t * 8 + g;       // fast index into B planes

    // ---- x state lives in registers in GEMM3-fragment layout ----
    float xr[4];
    {
        int colb = nt3 * 8 + t * 2;
        const float* p = x0 + (long)(row0 + r0l) * S_ + colb;
        xr[0] = p[0];
        xr[1] = p[1];
        xr[2] = p[8 * S_];
        xr[3] = p[8 * S_ + 1];
        int pidx = nt3 * 4 + t;
        xb[r0l * XSTR + pidx]       = pack_bf16(xr[0], xr[1]);
        xb[(r0l + 8) * XSTR + pidx] = pack_bf16(xr[2], xr[3]);
    }
    __syncthreads();

    // ======================= main time-step loop ==========================
    for (int step = 0; step < nsteps; ++step) {
        float acc[4][4];

        // ---- GEMM1: [16,64] @ W1[64,256] (per m-tile) ----
#pragma unroll
        for (int j = 0; j < 4; ++j)
#pragma unroll
            for (int q = 0; q < 4; ++q) acc[j][q] = 0.f;

#pragma unroll
        for (int kb = 0; kb < 4; ++kb) {
            const uint32_t* ap = xb + r0l * XSTR + kb * 8 + t;
            uint32_t a0 = ap[0], a2 = ap[4];
            uint32_t a1 = ap[8 * XSTR], a3 = ap[8 * XSTR + 4];
#pragma unroll
            for (int j = 0; j < 4; ++j) {
                int idx = ((nt1_0 + j) * 4 + kb) * 32 + tg;
                mma16816(acc[j], a0, a1, a2, a3, w1p0[idx], w1p1[idx]);
            }
        }
        // epilogue1: h = tanh(acc + b1)
#pragma unroll
        for (int j = 0; j < 4; ++j) {
            int colb = (nt1_0 + j) * 8 + t * 2;
            float bb0 = sb1[colb], bb1 = sb1[colb + 1];
            int pidx = (nt1_0 + j) * 4 + t;
            hbuf[r0l * HSTR + pidx] =
                pack_bf16(tanh_ap(acc[j][0] + bb0), tanh_ap(acc[j][1] + bb1));
            hbuf[(r0l + 8) * HSTR + pidx] =
                pack_bf16(tanh_ap(acc[j][2] + bb0), tanh_ap(acc[j][3] + bb1));
        }
        bar_mt(mt);

        // ---- GEMM2: [16,256] @ W2[256,256] ----
#pragma unroll
        for (int j = 0; j < 4; ++j)
#pragma unroll
            for (int q = 0; q < 4; ++q) acc[j][q] = 0.f;

#pragma unroll 4
        for (int kb = 0; kb < 16; ++kb) {
            const uint32_t* ap = hbuf + r0l * HSTR + kb * 8 + t;
            uint32_t a0 = ap[0], a2 = ap[4];
            uint32_t a1 = ap[8 * HSTR], a3 = ap[8 * HSTR + 4];
#pragma unroll
            for (int j = 0; j < 4; ++j) {
                int idx = ((nt1_0 + j) * 16 + kb) * 32 + tg;
                mma16816(acc[j], a0, a1, a2, a3, w2p0[idx], w2p1[idx]);
            }
        }
        bar_mt(mt);   // all reads of hbuf (this m-tile) done before overwrite

        // epilogue2: h = tanh(acc + b2) (in place)
#pragma unroll
        for (int j = 0; j < 4; ++j) {
            int colb = (nt1_0 + j) * 8 + t * 2;
            float bb0 = sb2[colb], bb1 = sb2[colb + 1];
            int pidx = (nt1_0 + j) * 4 + t;
            hbuf[r0l * HSTR + pidx] =
                pack_bf16(tanh_ap(acc[j][0] + bb0), tanh_ap(acc[j][1] + bb1));
            hbuf[(r0l + 8) * HSTR + pidx] =
                pack_bf16(tanh_ap(acc[j][2] + bb0), tanh_ap(acc[j][3] + bb1));
        }
        bar_mt(mt);

        // ---- GEMM3: [16,256] @ W3[256,64] ----
        float acc3[4];
#pragma unroll
        for (int q = 0; q < 4; ++q) acc3[q] = 0.f;

#pragma unroll 4
        for (int kb = 0; kb < 16; ++kb) {
            const uint32_t* ap = hbuf + r0l * HSTR + kb * 8 + t;
            uint32_t a0 = ap[0], a2 = ap[4];
            uint32_t a1 = ap[8 * HSTR], a3 = ap[8 * HSTR + 4];
            int idx = (nt3 * 16 + kb) * 32 + tg;
            mma16816(acc3, a0, a1, a2, a3, w3p0[idx], w3p1[idx]);
        }

        // epilogue3: x += (acc3 + b3) * dts ; write trajectory + refresh xb
        float* orow = out + (long)(row0 + r0l) * ostride + (long)(step + 1) * S_;
        {
            int colb = nt3 * 8 + t * 2;
            float bb0 = sb3[colb], bb1 = sb3[colb + 1];
            xr[0] += (acc3[0] + bb0) * dts;
            xr[1] += (acc3[1] + bb1) * dts;
            xr[2] += (acc3[2] + bb0) * dts;
            xr[3] += (acc3[3] + bb1) * dts;
            __stcs(reinterpret_cast<float2*>(orow + colb),
                   make_float2(xr[0], xr[1]));
            __stcs(reinterpret_cast<float2*>(orow + colb + 8 * ostride),
                   make_float2(xr[2], xr[3]));
            int pidx = nt3 * 4 + t;
            xb[r0l * XSTR + pidx]       = pack_bf16(xr[0], xr[1]);
            xb[(r0l + 8) * XSTR + pidx] = pack_bf16(xr[2], xr[3]);
        }
        bar_mt(mt);
    }
}

extern "C" void kernel_launch(void* const* d_in, const int* in_sizes, int n_in,
                              void* d_out, int out_size)
{
    (void)in_sizes; (void)n_in; (void)out_size;
    const float* x0       = (const float*)d_in[0];
    const float* W1       = (const float*)d_in[1];
    const float* b1       = (const float*)d_in[2];
    const float* W2       = (const float*)d_in[3];
    const float* b2       = (const float*)d_in[4];
    const float* W3       = (const float*)d_in[5];
    const float* b3       = (const float*)d_in[6];
    const float* dt_scale = (const float*)d_in[7];
    const int*   nsteps   = (const int*)d_in[8];
    float*       out      = (float*)d_out;

    cudaFuncSetAttribute(neuralode_persistent_kernel,
                         cudaFuncAttributeMaxDynamicSharedMemorySize, SMEM_BYTES);
    neuralode_persistent_kernel<<<CTAS, NTH, SMEM_BYTES>>>(
        x0, W1, b1, W2, b2, W3, b3, dt_scale, nsteps, out);
}

// round 3
// speedup vs baseline: 1.3516x; 1.2985x over previous
#include <cuda_runtime.h>
#include <cuda_bf16.h>
#include <cstdint>

// ---------------------------------------------------------------------------
// NeuralODE persistent kernel, round 3:
//  - 8 warps / 256 threads, each warp owns 4 n-tiles for BOTH m-tiles
//  - W2/W3 B-fragments register-resident (loaded once, reused 200 steps)
//  - W1 B-fragments from smem (cheap: 32 LDS/step/warp)
//  - biases in registers; smem traffic/step now below tensor-pipe floor
// ---------------------------------------------------------------------------

namespace {

constexpr int B_    = 4096;
constexpr int S_    = 64;
constexpr int H_    = 256;
constexpr int MROWS = 32;              // rows per CTA
constexpr int CTAS  = B_ / MROWS;      // 128
constexpr int NTH   = 256;             // 8 warps

// u32 strides (stride % 8 == 4 -> conflict-free A-fragment loads)
constexpr int HSTR = 132;
constexpr int XSTR = 36;

// smem layout (bytes)
constexpr int SM_W1P0 = 0;                           // 16384
constexpr int SM_W1P1 = SM_W1P0 + 16384;
constexpr int SM_W2P0 = SM_W1P1 + 16384;             // 65536 (used once)
constexpr int SM_W2P1 = SM_W2P0 + 65536;
constexpr int SM_W3P0 = SM_W2P1 + 65536;             // 16384 (used once)
constexpr int SM_W3P1 = SM_W3P0 + 16384;
constexpr int SM_H    = SM_W3P1 + 16384;             // 16896
constexpr int SM_XB   = SM_H + MROWS * HSTR * 4;     // 4608
constexpr int SMEM_BYTES = SM_XB + MROWS * XSTR * 4 + 256;

__device__ __forceinline__ uint32_t pack_bf16(float lo, float hi) {
    __nv_bfloat162 v = __floats2bfloat162_rn(lo, hi);
    return *reinterpret_cast<uint32_t*>(&v);
}

__device__ __forceinline__ float tanh_ap(float x) {
    float y;
    asm("tanh.approx.f32 %0, %1;" : "=f"(y) : "f"(x));
    return y;
}

__device__ __forceinline__ void mma16816(float* d,
                                         uint32_t a0, uint32_t a1, uint32_t a2, uint32_t a3,
                                         uint32_t b0, uint32_t b1) {
    asm volatile(
        "mma.sync.aligned.m16n8k16.row.col.f32.bf16.bf16.f32 "
        "{%0,%1,%2,%3},{%4,%5,%6,%7},{%8,%9},{%0,%1,%2,%3};\n"
        : "+f"(d[0]), "+f"(d[1]), "+f"(d[2]), "+f"(d[3])
        : "r"(a0), "r"(a1), "r"(a2), "r"(a3), "r"(b0), "r"(b1));
}

// Shuffle fp32 W[K][N] (row-major) into one bf16x2 B-fragment plane.
//   idx = ((nt*NKB + kb)*4 + t)*8 + g ; n = nt*8+g ; k0 = kb*16 + t*2 + koff
template <int NKB, int LOG2NKB>
__device__ void fill_plane(uint32_t* plane, const float* __restrict__ W,
                           int N, int koff, int tid) {
    const int total = N * NKB * 4;
    for (int e = tid; e < total; e += NTH) {
        int gg   = e & 7;
        int tt   = (e >> 3) & 3;
        int kbnt = e >> 5;
        int kb   = kbnt & (NKB - 1);
        int nt   = kbnt >> LOG2NKB;
        int n    = nt * 8 + gg;
        int k0   = kb * 16 + tt * 2 + koff;
        plane[e] = pack_bf16(W[k0 * N + n], W[(k0 + 1) * N + n]);
    }
}

} // namespace

extern "C" __global__ void __launch_bounds__(NTH, 1)
neuralode_persistent_kernel(const float* __restrict__ x0,
                            const float* __restrict__ W1, const float* __restrict__ b1,
                            const float* __restrict__ W2, const float* __restrict__ b2,
                            const float* __restrict__ W3, const float* __restrict__ b3,
                            const float* __restrict__ dt_scale,
                            const int*   __restrict__ num_steps,
                            float* __restrict__ out)
{
    extern __shared__ unsigned char smem_raw[];
    uint32_t* w1p0 = reinterpret_cast<uint32_t*>(smem_raw + SM_W1P0);
    uint32_t* w1p1 = reinterpret_cast<uint32_t*>(smem_raw + SM_W1P1);
    uint32_t* w2p0 = reinterpret_cast<uint32_t*>(smem_raw + SM_W2P0);
    uint32_t* w2p1 = reinterpret_cast<uint32_t*>(smem_raw + SM_W2P1);
    uint32_t* w3p0 = reinterpret_cast<uint32_t*>(smem_raw + SM_W3P0);
    uint32_t* w3p1 = reinterpret_cast<uint32_t*>(smem_raw + SM_W3P1);
    uint32_t* hbuf = reinterpret_cast<uint32_t*>(smem_raw + SM_H);
    uint32_t* xb   = reinterpret_cast<uint32_t*>(smem_raw + SM_XB);

    const int tid = threadIdx.x;

    // ---- one-time weight shuffle into fragment-ordered smem planes ----
    fill_plane<4, 2>(w1p0, W1, H_, 0, tid);
    fill_plane<4, 2>(w1p1, W1, H_, 8, tid);
    fill_plane<16, 4>(w2p0, W2, H_, 0, tid);
    fill_plane<16, 4>(w2p1, W2, H_, 8, tid);
    fill_plane<16, 4>(w3p0, W3, S_, 0, tid);
    fill_plane<16, 4>(w3p1, W3, S_, 8, tid);

    const int   nsteps  = num_steps[0];
    const float dts     = dt_scale[0] * 0.01f;
    const int   row0    = blockIdx.x * MROWS;
    const long  ostride = (long)(nsteps + 1) * S_;

    // ---- t=0: trajectory[., 0, .] = x0 ----
    for (int i = tid; i < MROWS * S_; i += NTH) {
        int r = i >> 6, c = i & 63;
        out[(long)(row0 + r) * ostride + c] = x0[(row0 + r) * S_ + c];
    }

    // ---- warp/lane decomposition: 8 warps, each 4 n-groups x 2 m-tiles ----
    const int warp = tid >> 5, lane = tid & 31;
    const int g = lane >> 2, t = lane & 3;
    const int ng  = warp;              // 0..7 column group
    const int tg  = t * 8 + g;

    __syncthreads();   // planes ready

    // ---- register-resident weight fragments (constant over all steps) ----
    uint32_t wb2a[4][16], wb2b[4][16];
#pragma unroll
    for (int j = 0; j < 4; ++j)
#pragma unroll
        for (int kb = 0; kb < 16; ++kb) {
            int idx = ((ng * 4 + j) * 16 + kb) * 32 + tg;
            wb2a[j][kb] = w2p0[idx];
            wb2b[j][kb] = w2p1[idx];
        }
    uint32_t wb3a[16], wb3b[16];
#pragma unroll
    for (int kb = 0; kb < 16; ++kb) {
        int idx = (ng * 16 + kb) * 32 + tg;
        wb3a[kb] = w3p0[idx];
        wb3b[kb] = w3p1[idx];
    }

    // ---- register-resident biases (fragment layout) ----
    float pb1[4][2], pb2[4][2], pb3[2];
#pragma unroll
    for (int j = 0; j < 4; ++j) {
        int c = (ng * 4 + j) * 8 + t * 2;
        pb1[j][0] = b1[c];     pb1[j][1] = b1[c + 1];
        pb2[j][0] = b2[c];     pb2[j][1] = b2[c + 1];
    }
    {
        int c = ng * 8 + t * 2;
        pb3[0] = b3[c]; pb3[1] = b3[c + 1];
    }

    // ---- x state in registers (GEMM3-fragment layout, both m-tiles) ----
    float xr[2][4];
#pragma unroll
    for (int mt = 0; mt < 2; ++mt) {
        int r = mt * 16 + g;
        int colb = ng * 8 + t * 2;
        const float* p = x0 + (long)(row0 + r) * S_ + colb;
        xr[mt][0] = p[0];
        xr[mt][1] = p[1];
        xr[mt][2] = p[8 * S_];
        xr[mt][3] = p[8 * S_ + 1];
        int pidx = ng * 4 + t;
        xb[r * XSTR + pidx]       = pack_bf16(xr[mt][0], xr[mt][1]);
        xb[(r + 8) * XSTR + pidx] = pack_bf16(xr[mt][2], xr[mt][3]);
    }
    __syncthreads();

    // ======================= main time-step loop ==========================
    for (int step = 0; step < nsteps; ++step) {
        float acc[2][4][4];

        // ---- GEMM1: [32,64] @ W1[64,256] (B frags from smem) ----
#pragma unroll
        for (int mt = 0; mt < 2; ++mt)
#pragma unroll
            for (int j = 0; j < 4; ++j)
#pragma unroll
                for (int q = 0; q < 4; ++q) acc[mt][j][q] = 0.f;

#pragma unroll
        for (int kb = 0; kb < 4; ++kb) {
            uint32_t a[2][4];
#pragma unroll
            for (int mt = 0; mt < 2; ++mt) {
                const uint32_t* ap = xb + (mt * 16 + g) * XSTR + kb * 8 + t;
                a[mt][0] = ap[0];
                a[mt][2] = ap[4];
                a[mt][1] = ap[8 * XSTR];
                a[mt][3] = ap[8 * XSTR + 4];
            }
#pragma unroll
            for (int j = 0; j < 4; ++j) {
                int idx = ((ng * 4 + j) * 4 + kb) * 32 + tg;
                uint32_t b0 = w1p0[idx], b1f = w1p1[idx];
#pragma unroll
                for (int mt = 0; mt < 2; ++mt)
                    mma16816(acc[mt][j], a[mt][0], a[mt][1], a[mt][2], a[mt][3],
                             b0, b1f);
            }
        }
        // epilogue1: h = tanh(acc + b1)
#pragma unroll
        for (int mt = 0; mt < 2; ++mt)
#pragma unroll
            for (int j = 0; j < 4; ++j) {
                int pidx = (ng * 4 + j) * 4 + t;
                int r = mt * 16 + g;
                hbuf[r * HSTR + pidx] =
                    pack_bf16(tanh_ap(acc[mt][j][0] + pb1[j][0]),
                              tanh_ap(acc[mt][j][1] + pb1[j][1]));
                hbuf[(r + 8) * HSTR + pidx] =
                    pack_bf16(tanh_ap(acc[mt][j][2] + pb1[j][0]),
                              tanh_ap(acc[mt][j][3] + pb1[j][1]));
            }
        __syncthreads();

        // ---- GEMM2: [32,256] @ W2[256,256] (B frags in registers) ----
#pragma unroll
        for (int mt = 0; mt < 2; ++mt)
#pragma unroll
            for (int j = 0; j < 4; ++j)
#pragma unroll
                for (int q = 0; q < 4; ++q) acc[mt][j][q] = 0.f;

#pragma unroll
        for (int kb = 0; kb < 16; ++kb) {
            uint32_t a[2][4];
#pragma unroll
            for (int mt = 0; mt < 2; ++mt) {
                const uint32_t* ap = hbuf + (mt * 16 + g) * HSTR + kb * 8 + t;
                a[mt][0] = ap[0];
                a[mt][2] = ap[4];
                a[mt][1] = ap[8 * HSTR];
                a[mt][3] = ap[8 * HSTR + 4];
            }
#pragma unroll
            for (int j = 0; j < 4; ++j)
#pragma unroll
                for (int mt = 0; mt < 2; ++mt)
                    mma16816(acc[mt][j], a[mt][0], a[mt][1], a[mt][2], a[mt][3],
                             wb2a[j][kb], wb2b[j][kb]);
        }
        __syncthreads();   // all reads of hbuf done before overwrite

        // epilogue2: h = tanh(acc + b2) (in place)
#pragma unroll
        for (int mt = 0; mt < 2; ++mt)
#pragma unroll
            for (int j = 0; j < 4; ++j) {
                int pidx = (ng * 4 + j) * 4 + t;
                int r = mt * 16 + g;
                hbuf[r * HSTR + pidx] =
                    pack_bf16(tanh_ap(acc[mt][j][0] + pb2[j][0]),
                              tanh_ap(acc[mt][j][1] + pb2[j][1]));
                hbuf[(r + 8) * HSTR + pidx] =
                    pack_bf16(tanh_ap(acc[mt][j][2] + pb2[j][0]),
                              tanh_ap(acc[mt][j][3] + pb2[j][1]));
            }
        __syncthreads();

        // ---- GEMM3: [32,256] @ W3[256,64] (B frags in registers) ----
        float acc3[2][4];
#pragma unroll
        for (int mt = 0; mt < 2; ++mt)
#pragma unroll
            for (int q = 0; q < 4; ++q) acc3[mt][q] = 0.f;

#pragma unroll
        for (int kb = 0; kb < 16; ++kb) {
#pragma unroll
            for (int mt = 0; mt < 2; ++mt) {
                const uint32_t* ap = hbuf + (mt * 16 + g) * HSTR + kb * 8 + t;
                mma16816(acc3[mt], ap[0], ap[8 * HSTR], ap[4], ap[8 * HSTR + 4],
                         wb3a[kb], wb3b[kb]);
            }
        }

        // epilogue3: x += (acc3 + b3) * dts ; trajectory store + xb refresh
#pragma unroll
        for (int mt = 0; mt < 2; ++mt) {
            int r = mt * 16 + g;
            int colb = ng * 8 + t * 2;
            xr[mt][0] += (acc3[mt][0] + pb3[0]) * dts;
            xr[mt][1] += (acc3[mt][1] + pb3[1]) * dts;
            xr[mt][2] += (acc3[mt][2] + pb3[0]) * dts;
            xr[mt][3] += (acc3[mt][3] + pb3[1]) * dts;
            float* orow = out + (long)(row0 + r) * ostride
                        + (long)(step + 1) * S_ + colb;
            __stcs(reinterpret_cast<float2*>(orow),
                   make_float2(xr[mt][0], xr[mt][1]));
            __stcs(reinterpret_cast<float2*>(orow + 8 * ostride),
                   make_float2(xr[mt][2], xr[mt][3]));
            int pidx = ng * 4 + t;
            xb[r * XSTR + pidx]       = pack_bf16(xr[mt][0], xr[mt][1]);
            xb[(r + 8) * XSTR + pidx] = pack_bf16(xr[mt][2], xr[mt][3]);
        }
        __syncthreads();
    }
}

extern "C" void kernel_launch(void* const* d_in, const int* in_sizes, int n_in,
                              void* d_out, int out_size)
{
    (void)in_sizes; (void)n_in; (void)out_size;
    const float* x0       = (const float*)d_in[0];
    const float* W1       = (const float*)d_in[1];
    const float* b1       = (const float*)d_in[2];
    const float* W2       = (const float*)d_in[3];
    const float* b2       = (const float*)d_in[4];
    const float* W3       = (const float*)d_in[5];
    const float* b3       = (const float*)d_in[6];
    const float* dt_scale = (const float*)d_in[7];
    const int*   nsteps   = (const int*)d_in[8];
    float*       out      = (float*)d_out;

    cudaFuncSetAttribute(neuralode_persistent_kernel,
                         cudaFuncAttributeMaxDynamicSharedMemorySize, SMEM_BYTES);
    neuralode_persistent_kernel<<<CTAS, NTH, SMEM_BYTES>>>(
        x0, W1, b1, W2, b2, W3, b3, dt_scale, nsteps, out);
}